// round 16
// baseline (speedup 1.0000x reference)
#include <cuda_runtime.h>
#include <cuda_bf16.h>

// Problem constants
#define NB   32
#define NN   8400
#define NCLS 80
#define NCF  (NN * NCLS)       // 672000 scores per batch
#define TOPK 1024
#define CAP  8192
#define NDET 300
#define THRS 0.001f
#define IOUT 0.7f

#define CLO    0.96875f        // high-region lower bound (31/32, exact fp32)
#define NBINS  32768           // cold-path fine bins
#define HWORDS 16384           // fine bins packed as u16 pairs (64 KB)
#define NB2    1024            // selection bins (10-bit)
#define BINCAP 64              // slots per bin (lambda ~21)
#define HSLICES 16
#define CAPB   (NB2 * BINCAP)  // 65536: cold path reuses bin storage linearly

// ---------------- scratch (device globals; no allocation allowed) ----------
__device__ unsigned int        g_coarse[NB * NB2];        // count+allocator; self-reset
__device__ __align__(16) unsigned long long g_cand[NB * NB2 * BINCAP];  // 16 MB

// 21-bit hi-region value: (s-CLO) is exact (Sterbenz), *2^21 exact (pow2).
__device__ __forceinline__ unsigned v21(float s) {
    unsigned v = (unsigned)(__fmul_rn(__fsub_rn(s, CLO), 2097152.0f));
    return v > 65535u ? 65535u : v;
}
__device__ __forceinline__ unsigned binhi10(float s) { return v21(s) >> 6; }  // 0..1023
// full-range bin (cold path): 0 for masked scores, else monotonic
__device__ __forceinline__ unsigned binlo2(float s) {
    if (!(s > THRS)) return 0u;
    unsigned b = (unsigned)(s * 32768.0f);
    return b > (NBINS - 1) ? (NBINS - 1) : b;
}

// ---------------- kernel 1: scan -> bin-segmented candidates ----------------
// grid (HSLICES, NB), 1024 threads, zero smem. g_coarse[bin] is count+allocator.
__global__ void __launch_bounds__(1024) k_scan(const float4* __restrict__ s4) {
    const int b = blockIdx.y, s = blockIdx.x, t = threadIdx.x;
    const int perb4 = NCF / 4;                 // 168000
    const int slice = perb4 / HSLICES;         // 10500
    const float4* src = s4 + (size_t)b * perb4 + (size_t)s * slice;
    const unsigned idx0 = (unsigned)((s * slice + t) * 4);
    unsigned* cnts = g_coarse + b * NB2;
    unsigned long long* cbase = g_cand + (size_t)b * NB2 * BINCAP;

    #pragma unroll
    for (int g = 0; g < 10; g++) {
        float4 a = src[g * 1024 + t];
        float mx = fmaxf(fmaxf(a.x, a.y), fmaxf(a.z, a.w));
        if (mx > CLO) {
            float c[4] = {a.x, a.y, a.z, a.w};
            #pragma unroll
            for (int q = 0; q < 4; q++) {
                if (c[q] > CLO) {
                    unsigned bin = binhi10(c[q]);
                    unsigned pos = atomicAdd(&cnts[bin], 1u);
                    if (pos < BINCAP)
                        cbase[((size_t)bin << 6) + pos] =
                            ((unsigned long long)__float_as_uint(c[q]) << 32)
                            | (unsigned long long)(~(idx0 + g * 4096u + q));
                }
            }
        }
    }
    if (t < slice - 10240) {
        float4 a = src[10240 + t];
        float mx = fmaxf(fmaxf(a.x, a.y), fmaxf(a.z, a.w));
        if (mx > CLO) {
            float c[4] = {a.x, a.y, a.z, a.w};
            #pragma unroll
            for (int q = 0; q < 4; q++) {
                if (c[q] > CLO) {
                    unsigned bin = binhi10(c[q]);
                    unsigned pos = atomicAdd(&cnts[bin], 1u);
                    if (pos < BINCAP)
                        cbase[((size_t)bin << 6) + pos] =
                            ((unsigned long long)__float_as_uint(c[q]) << 32)
                            | (unsigned long long)(~(idx0 + 40960u + q));
                }
            }
        }
    }
}

// bitonic register step: element index i, phase k2, distance j (<32)
__device__ __forceinline__ unsigned long long bstep(
    unsigned long long v, int i, int k2, int j) {
    unsigned long long o = __shfl_xor_sync(0xffffffffu, v, j);
    bool keepmax = (((i & k2) == 0) == ((i & j) == 0));
    unsigned long long mx = v > o ? v : o;
    unsigned long long mn = v > o ? o : v;
    return keepmax ? mx : mn;
}

// one-warp: load cnt (<=64) keys from src, sort descending, store to dst
__device__ __forceinline__ void warp_sort64(const unsigned long long* __restrict__ src,
                                            unsigned long long* dst, int cnt, int lane) {
    unsigned long long v0 = (lane < cnt) ? src[lane] : 0ull;
    unsigned long long v1 = (lane + 32 < cnt) ? src[lane + 32] : 0ull;
    const int e0 = lane, e1 = lane + 32;
    #pragma unroll
    for (int k2 = 2; k2 <= 32; k2 <<= 1)
        #pragma unroll
        for (int j = k2 >> 1; j >= 1; j >>= 1) {
            v0 = bstep(v0, e0, k2, j);
            v1 = bstep(v1, e1, k2, j);
        }
    // k2 = 64, j = 32: cross-register (desc for all i<64; r0 keeps max)
    {
        unsigned long long mx = v0 > v1 ? v0 : v1;
        unsigned long long mn = v0 > v1 ? v1 : v0;
        v0 = mx; v1 = mn;
    }
    #pragma unroll
    for (int j = 16; j >= 1; j >>= 1) {
        v0 = bstep(v0, e0, 64, j);
        v1 = bstep(v1, e1, 64, j);
    }
    if (lane < cnt) dst[lane] = v0;
    if (lane + 32 < cnt) dst[lane + 32] = v1;
}

// ---------------- kernel 2: layout + per-warp bin sorts + NMS + output ------
// key u64 = (float_bits << 32) | ~flat_idx, descending ->
// score desc, flat idx ascending on ties (matches lax.top_k stability).
// Cross-class IoU is exactly 0 (class offset gap), so global greedy ==
// independent per-class greedy in global-rank order. IoU ops identical to
// reference: offset coords, strict > 0.7, __f*_rn arithmetic.
__global__ void __launch_bounds__(1024) k_sortnms(const float4* __restrict__ boxes,
                                                  const float4* __restrict__ s4,
                                                  float* __restrict__ out) {
    extern __shared__ unsigned long long sm[];       // CAP u64 = 64 KB dynamic
    __shared__ int scnt, sT, sSuffT, sMaxSeg, sRaw;
    __shared__ unsigned sstart[NB2];                 // 4 KB
    __shared__ float4 sbox[TOPK];                    // 16 KB
    __shared__ float sy1[TOPK], sx1[TOPK], sy2[TOPK], sx2[TOPK], sa[TOPK];
    __shared__ float ssc[TOPK];
    __shared__ short scls[TOPK];
    __shared__ unsigned short wcount[NCLS * 32];
    __shared__ unsigned short wbase [NCLS * 32];
    __shared__ unsigned short ctot[NCLS];
    __shared__ unsigned short cstart[NCLS];
    __shared__ unsigned short list[TOPK];
    __shared__ unsigned char  skept[TOPK];
    __shared__ unsigned kw[32];
    __shared__ int kpref[33];

    int b = blockIdx.x;
    int t = threadIdx.x;
    int warp = t >> 5, lane = t & 31;
    const int perb4 = NCF / 4;

    if (t == 0) { scnt = 0; sT = 0; sSuffT = 0; sMaxSeg = 0; sRaw = 0; }
    sstart[t] = g_coarse[b * NB2 + t];               // exact counts
    __syncthreads();

    unsigned long long* cand = g_cand + (size_t)b * NB2 * BINCAP;
    bool hot = false;

    // ---- warp-0: in-place suffix layout over 1024 bins ----
    if (warp == 0) {
        unsigned gsum = 0;
        #pragma unroll
        for (int k = 0; k < 32; k++) gsum += sstart[lane * 32 + k];
        unsigned acc = gsum;
        #pragma unroll
        for (int off = 1; off < 32; off <<= 1) {
            unsigned y = __shfl_down_sync(0xffffffffu, acc, off);
            if (lane + off < 32) acc += y;
        }
        unsigned total = __shfl_sync(0xffffffffu, acc, 0);
        unsigned above = acc - gsum;
        unsigned run = above;
        int localT = -1;
        unsigned localSuff = 0;
        #pragma unroll
        for (int k = 31; k >= 0; k--) {
            int bin = lane * 32 + k;
            unsigned cv = sstart[bin];
            sstart[bin] = run;                       // start offset (suffix layout)
            run += cv;
            if (localT < 0 && run >= TOPK) { localT = bin; localSuff = run; }
        }
        unsigned mb = __ballot_sync(0xffffffffu, localT >= 0);
        int T = 0; unsigned suffT = total;
        if (mb) {
            int selLane = 31 - __clz((int)mb);
            T = __shfl_sync(0xffffffffu, localT, selLane);
            suffT = __shfl_sync(0xffffffffu, (unsigned)localSuff, selLane);
        }
        __syncwarp();
        unsigned mx = 0;
        for (int bin = T + lane; bin < NB2; bin += 32) {
            unsigned up = (bin == 0) ? total : sstart[bin - 1];
            unsigned cv = up - sstart[bin];
            if (cv > mx) mx = cv;
        }
        #pragma unroll
        for (int off = 16; off >= 1; off >>= 1)
            mx = max(mx, __shfl_xor_sync(0xffffffffu, mx, off));
        if (lane == 0) { sT = T; sSuffT = (int)suffT; sMaxSeg = (int)mx; sRaw = (int)total; }
    }
    __syncthreads();
    const int T = sT;
    const int suffT = sSuffT;
    const int rawcnt = sRaw;
    hot = (rawcnt >= TOPK) && (sMaxSeg <= BINCAP) && (suffT <= CAP);

    if (hot) {
        // ---- per-warp: load bin segment from gmem, register-sort, store ----
        for (int bin = T + warp; bin < NB2; bin += 32) {
            unsigned st = sstart[bin];
            unsigned up = (bin == 0) ? (unsigned)rawcnt : sstart[bin - 1];
            int cnt = (int)(up - st);
            if (cnt > 0)
                warp_sort64(cand + ((size_t)bin << 6), sm + st, cnt, lane);
        }
        __syncthreads();
    } else {
        // ---- cold: full-range fine histogram + collect (always correct) ----
        unsigned* sh = (unsigned*)sm;                // 64 KB = HWORDS u32
        for (int i = t; i < HWORDS; i += 1024) sh[i] = 0;
        __syncthreads();
        const float4* src = s4 + (size_t)b * perb4;
        for (int i = t; i < perb4; i += 1024) {
            float4 v = src[i];
            float comp[4] = {v.x, v.y, v.z, v.w};
            #pragma unroll
            for (int q = 0; q < 4; q++) {
                unsigned k = binlo2(comp[q]);
                atomicAdd(&sh[k >> 1], 1u << ((k & 1) * 16));
            }
        }
        __syncthreads();
        if (t < 256) {
            unsigned sum = 0;
            for (int k = 0; k < 64; k++) {
                unsigned m = sh[t * 64 + k];
                sum += (m & 0xFFFFu) + (m >> 16);
            }
            sstart[t] = sum;
        }
        __syncthreads();
        if (t == 0) {
            unsigned h0 = sh[0] & 0xFFFFu;
            int sel = -1; unsigned cum = 0, cums = 0;
            for (int c = 255; c >= 0; c--) {
                unsigned cc = sstart[c] - (c == 0 ? h0 : 0u);
                if (cum + cc >= TOPK) { sel = c; cums = cum; break; }
                cum += cc;
            }
            int Tc = 1;
            if (sel >= 0) {
                unsigned cum2 = cums;
                int lo = (sel == 0) ? 1 : 0;
                for (int fb = 127; fb >= lo; fb--) {
                    int bin = (sel << 7) + fb;
                    unsigned m = sh[bin >> 1];
                    unsigned cc = (bin & 1) ? (m >> 16) : (m & 0xFFFFu);
                    cum2 += cc;
                    if (cum2 >= TOPK) { Tc = bin; break; }
                }
            }
            sT = Tc;
        }
        __syncthreads();
        unsigned Tc = (unsigned)sT;
        for (int i = t; i < perb4; i += 1024) {
            float4 v = src[i];
            float comp[4] = {v.x, v.y, v.z, v.w};
            #pragma unroll
            for (int q = 0; q < 4; q++) {
                float sv = comp[q];
                if (binlo2(sv) >= Tc) {
                    int p = atomicAdd(&scnt, 1);
                    if (p < CAPB) {
                        unsigned idx = (unsigned)(i * 4 + q);
                        cand[p] = ((unsigned long long)__float_as_uint(sv) << 32)
                                | (unsigned long long)(~idx);
                    }
                }
            }
        }
        __syncthreads();
        int cc = scnt; if (cc > CAP) cc = CAP;
        for (int i = t; i < cc; i += 1024) sm[i] = cand[i];
        __syncthreads();
        int n2 = 2048;
        while (n2 < cc) n2 <<= 1;
        for (int i = t; i < n2; i += 1024) if (i >= cc) sm[i] = 0ull;
        __syncthreads();
        for (int k2 = 2; k2 <= n2; k2 <<= 1) {
            for (int j = k2 >> 1; j > 0; j >>= 1) {
                for (int i = t; i < n2; i += 1024) {
                    int ixj = i ^ j;
                    if (ixj > i) {
                        unsigned long long x = sm[i], y = sm[ixj];
                        bool desc = ((i & k2) == 0);
                        if (desc ? (x < y) : (x > y)) { sm[i] = y; sm[ixj] = x; }
                    }
                }
                __syncthreads();
            }
        }
    }

    // ---- gather top-1024 boxes + build offset coords ----
    {
        unsigned long long kk = sm[t];
        unsigned keyhi = (unsigned)(kk >> 32);
        float4 bx = make_float4(0.f, 0.f, 0.f, 0.f);
        int cls = 0; float sc = 0.f;
        if (keyhi != 0) {
            unsigned idx = ~(unsigned)(kk & 0xFFFFFFFFull);
            int n = (int)(idx / NCLS);
            cls = (int)(idx % NCLS);
            sc = __uint_as_float(keyhi);
            bx = boxes[b * NN + n];
        }
        sbox[t] = bx; scls[t] = (short)cls; ssc[t] = sc;
        float off = (float)cls * 4096.0f;            // exact in fp32
        float y1 = __fadd_rn(bx.x, off);
        float x1 = __fadd_rn(bx.y, off);
        float y2 = __fadd_rn(bx.z, off);
        float x2 = __fadd_rn(bx.w, off);
        sy1[t] = y1; sx1[t] = x1; sy2[t] = y2; sx2[t] = x2;
        sa[t] = __fmul_rn(__fadd_rn(__fsub_rn(x2, x1), 1.0f),
                          __fadd_rn(__fsub_rn(y2, y1), 1.0f));
    }
    float sc = ssc[t];
    int c = scls[t];
    bool valid = (sc > THRS);
    unsigned bal = __ballot_sync(0xffffffff, valid);
    if (lane == 0) kw[warp] = bal;
    for (int i = t; i < NCLS * 32; i += 1024) wcount[i] = 0;
    skept[t] = 1;
    __syncthreads();

    // ---- stable per-class list build (parallel scans) ----
    int cc2 = valid ? c : 0x7FFF;
    unsigned mm = __match_any_sync(0xffffffffu, cc2);
    int rank = __popc(mm & ((1u << lane) - 1u));
    int ldr = __ffs(mm) - 1;
    if (valid && lane == ldr) wcount[cc2 * 32 + warp] = (unsigned short)__popc(mm);
    __syncthreads();
    for (int c2 = warp; c2 < NCLS; c2 += 32) {
        unsigned v = wcount[c2 * 32 + lane];
        unsigned x = v;
        #pragma unroll
        for (int o = 1; o < 32; o <<= 1) {
            unsigned y = __shfl_up_sync(0xffffffffu, x, o);
            if (lane >= o) x += y;
        }
        wbase[c2 * 32 + lane] = (unsigned short)(x - v);
        if (lane == 31) ctot[c2] = (unsigned short)x;
    }
    __syncthreads();
    if (warp == 0) {
        unsigned a0 = ctot[lane];
        unsigned a1 = ctot[lane + 32];
        unsigned a2 = (lane + 64 < NCLS) ? ctot[lane + 64] : 0u;
        unsigned s0 = a0, s1 = a1, s2 = a2;
        #pragma unroll
        for (int o = 1; o < 32; o <<= 1) {
            unsigned y0 = __shfl_up_sync(0xffffffffu, s0, o);
            unsigned y1 = __shfl_up_sync(0xffffffffu, s1, o);
            unsigned y2 = __shfl_up_sync(0xffffffffu, s2, o);
            if (lane >= o) { s0 += y0; s1 += y1; s2 += y2; }
        }
        unsigned A0 = __shfl_sync(0xffffffffu, s0, 31);
        unsigned A1 = __shfl_sync(0xffffffffu, s1, 31);
        cstart[lane]      = (unsigned short)(s0 - a0);
        cstart[lane + 32] = (unsigned short)(A0 + s1 - a1);
        if (lane + 64 < NCLS) cstart[lane + 64] = (unsigned short)(A0 + A1 + s2 - a2);
    }
    __syncthreads();
    if (valid) list[cstart[cc2] + wbase[cc2 * 32 + warp] + rank] = (unsigned short)t;
    __syncthreads();

    // ---- per-class greedy (one warp per class; two-phase shfl) ----
    for (int c2 = warp; c2 < NCLS; c2 += 32) {
        int m = ctot[c2];
        if (m < 2) continue;
        int base = cstart[c2];
        if (m <= 32) {
            int tj = 0;
            float jy1 = 0, jx1 = 0, jy2 = 0, jx2 = 0, ja = 0;
            bool inr = (lane < m);
            if (inr) {
                tj = list[base + lane];
                jy1 = sy1[tj]; jx1 = sx1[tj]; jy2 = sy2[tj]; jx2 = sx2[tj]; ja = sa[tj];
            }
            unsigned sup = 0;
            for (int i = 0; i < m - 1; i++) {
                float iy1 = __shfl_sync(0xffffffffu, jy1, i);
                float ix1 = __shfl_sync(0xffffffffu, jx1, i);
                float iy2 = __shfl_sync(0xffffffffu, jy2, i);
                float ix2 = __shfl_sync(0xffffffffu, jx2, i);
                float ia  = __shfl_sync(0xffffffffu, ja,  i);
                if (lane > i) {
                    float yy1 = fmaxf(iy1, jy1);
                    float xx1 = fmaxf(ix1, jx1);
                    float yy2 = fminf(iy2, jy2);
                    float xx2 = fminf(ix2, jx2);
                    float ww = fmaxf(0.0f, __fadd_rn(__fsub_rn(xx2, xx1), 1.0f));
                    float hh = fmaxf(0.0f, __fadd_rn(__fsub_rn(yy2, yy1), 1.0f));
                    float inter = __fmul_rn(ww, hh);
                    float iou = __fdiv_rn(inter, __fsub_rn(__fadd_rn(ia, ja), inter));
                    if (iou > IOUT) sup |= (1u << i);
                }
            }
            unsigned anysup = __ballot_sync(0xffffffffu, inr && sup != 0u);
            bool kept = inr;
            if (anysup) {
                unsigned keptmask = 0;
                for (int i = 0; i < m; i++) {
                    unsigned si = __shfl_sync(0xffffffffu, sup, i);
                    unsigned bit = ((si & keptmask) == 0u) ? 1u : 0u;
                    keptmask |= bit << i;
                }
                kept = inr && ((keptmask >> lane) & 1u);
            }
            if (inr && !kept) atomicAnd(&kw[tj >> 5], ~(1u << (tj & 31)));
        } else {
            for (int i = 0; i < m - 1; i++) {
                __syncwarp();
                if (!skept[base + i]) continue;
                int ti = list[base + i];
                float iy1 = sy1[ti], ix1 = sx1[ti], iy2 = sy2[ti], ix2 = sx2[ti], ia = sa[ti];
                for (int k = i + 1 + lane; k < m; k += 32) {
                    if (skept[base + k]) {
                        int tk = list[base + k];
                        float yy1 = fmaxf(iy1, sy1[tk]);
                        float xx1 = fmaxf(ix1, sx1[tk]);
                        float yy2 = fminf(iy2, sy2[tk]);
                        float xx2 = fminf(ix2, sx2[tk]);
                        float ww = fmaxf(0.0f, __fadd_rn(__fsub_rn(xx2, xx1), 1.0f));
                        float hh = fmaxf(0.0f, __fadd_rn(__fsub_rn(yy2, yy1), 1.0f));
                        float inter = __fmul_rn(ww, hh);
                        float iou = __fdiv_rn(inter, __fsub_rn(__fadd_rn(ia, sa[tk]), inter));
                        if (iou > IOUT) skept[base + k] = 0;
                    }
                }
            }
            __syncwarp();
            for (int k = lane; k < m; k += 32)
                if (!skept[base + k]) {
                    int tk = list[base + k];
                    atomicAnd(&kw[tk >> 5], ~(1u << (tk & 31)));
                }
        }
    }
    __syncthreads();

    // ---- ranking + output ----
    if (t < 32) {
        unsigned my = kw[t];
        int p = __popc(my);
        int x = p;
        #pragma unroll
        for (int o = 1; o < 32; o <<= 1) {
            int y = __shfl_up_sync(0xffffffff, x, o);
            if (t >= o) x += y;
        }
        kpref[t] = x - p;
        if (t == 31) kpref[32] = x;
    }
    __syncthreads();

    int w = t >> 5, l = t & 31;
    unsigned kwv = kw[w];
    bool kept = (kwv >> l) & 1u;
    unsigned lowm = (l == 0) ? 0u : ((1u << l) - 1u);
    int TKall = kpref[32];

    int slot = -1;
    float oscore = 0.0f;
    if (kept) {
        int kr = kpref[w] + __popc(kwv & lowm);
        if (kr < NDET) { slot = kr; oscore = sc; }
    } else {
        int sr = (w << 5) - kpref[w] + __popc((~kwv) & lowm);
        int s2 = TKall + sr;
        if (s2 < NDET) { slot = s2; oscore = 0.0f; }
    }

    // output layout (float32): boxes[32,300,4] | scores[32,300] | labels[32,300] | n_valid[32,1]
    if (slot >= 0) {
        float4 bx = sbox[t];
        float* ob = out + ((size_t)b * NDET + slot) * 4;
        ob[0] = bx.x; ob[1] = bx.y; ob[2] = bx.z; ob[3] = bx.w;
        out[NB * NDET * 4 + b * NDET + slot] = oscore;
        out[NB * NDET * 5 + b * NDET + slot] = (float)c;
    }
    // reset per-replay state
    g_coarse[b * NB2 + t] = 0;
    if (t == 0)
        out[NB * NDET * 6 + b] = (float)(TKall < NDET ? TKall : NDET);
}

// ---------------- launch ----------------------------------------------------
extern "C" void kernel_launch(void* const* d_in, const int* in_sizes, int n_in,
                              void* d_out, int out_size) {
    const float* boxes  = (const float*)d_in[0];
    const float* scores = (const float*)d_in[1];
    if (n_in >= 2 && in_sizes[0] > in_sizes[1]) {
        boxes  = (const float*)d_in[1];
        scores = (const float*)d_in[0];
    }
    float* out = (float*)d_out;

    cudaFuncSetAttribute(k_sortnms, cudaFuncAttributeMaxDynamicSharedMemorySize, CAP * 8);

    k_scan   <<<dim3(HSLICES, NB), 1024>>>((const float4*)scores);
    k_sortnms<<<NB, 1024, CAP * 8>>>((const float4*)boxes, (const float4*)scores, out);
}

// round 17
// speedup vs baseline: 1.2569x; 1.2569x over previous
#include <cuda_runtime.h>
#include <cuda_bf16.h>

// Problem constants
#define NB   32
#define NN   8400
#define NCLS 80
#define NCF  (NN * NCLS)       // 672000 scores per batch
#define TOPK 1024
#define CAP  8192
#define NDET 300
#define THRS 0.001f
#define IOUT 0.7f

#define CLO    0.96875f        // high-region lower bound (31/32, exact fp32)
#define NBINS  32768           // cold-path fine bins
#define HWORDS 16384           // fine bins packed as u16 pairs (64 KB)
#define NB2    1024            // hot-path selection bins (10-bit)
#define HSLICES 16
#define SEGCAP 128             // per-warp staging (expected ~41 hits)
#define CAPB   32768           // per-batch candidate buffer (expected ~21000)
#define CSTRIDE 256            // counter spacing (1 KB)

// ---------------- scratch (device globals; no allocation allowed) ----------
__device__ int                 g_cnt[NB * CSTRIDE];       // [b][0]=count, [b][1]=ovf
__device__ unsigned int        g_coarse[NB * NB2];        // zero-init; self-reset
__device__ __align__(16) unsigned long long g_cand[NB * CAPB];  // 8 MB

// 21-bit hi-region value: (s-CLO) is exact (Sterbenz), *2^21 exact (pow2).
__device__ __forceinline__ unsigned v21(float s) {
    unsigned v = (unsigned)(__fmul_rn(__fsub_rn(s, CLO), 2097152.0f));
    return v > 65535u ? 65535u : v;
}
__device__ __forceinline__ unsigned binhi10(float s) { return v21(s) >> 6; }  // 0..1023
// full-range bin (cold path): 0 for masked scores, else monotonic
__device__ __forceinline__ unsigned binlo2(float s) {
    if (!(s > THRS)) return 0u;
    unsigned b = (unsigned)(s * 32768.0f);
    return b > (NBINS - 1) ? (NBINS - 1) : b;
}

// ---------------- kernel 1: ballot-free scan + fine hist (R14-proven) -------
__global__ void __launch_bounds__(1024) k_scan(const float4* __restrict__ s4) {
    __shared__ unsigned long long stage[32 * SEGCAP];   // 32 KB
    __shared__ unsigned shc[NB2];                        // 4 KB
    __shared__ int wctr[32];
    __shared__ int woff[32];
    __shared__ int bbase;
    const int b = blockIdx.y, s = blockIdx.x, t = threadIdx.x;
    const int warp = t >> 5, lane = t & 31;
    shc[t] = 0;
    if (t < 32) wctr[t] = 0;
    __syncthreads();

    const int perb4 = NCF / 4;                 // 168000
    const int slice = perb4 / HSLICES;         // 10500
    const float4* src = s4 + (size_t)b * perb4 + (size_t)s * slice;
    const unsigned idx0 = (unsigned)((s * slice + t) * 4);
    unsigned long long* mystage = stage + warp * SEGCAP;

    #pragma unroll
    for (int g = 0; g < 10; g++) {
        float4 a = src[g * 1024 + t];
        float mx = fmaxf(fmaxf(a.x, a.y), fmaxf(a.z, a.w));
        if (mx > CLO) {
            float c[4] = {a.x, a.y, a.z, a.w};
            #pragma unroll
            for (int q = 0; q < 4; q++) {
                if (c[q] > CLO) {
                    atomicAdd(&shc[binhi10(c[q])], 1u);
                    int p = atomicAdd(&wctr[warp], 1);
                    if (p < SEGCAP)
                        mystage[p] = ((unsigned long long)__float_as_uint(c[q]) << 32)
                                   | (unsigned long long)(~(idx0 + g * 4096u + q));
                }
            }
        }
    }
    if (t < slice - 10240) {
        float4 a = src[10240 + t];
        float mx = fmaxf(fmaxf(a.x, a.y), fmaxf(a.z, a.w));
        if (mx > CLO) {
            float c[4] = {a.x, a.y, a.z, a.w};
            #pragma unroll
            for (int q = 0; q < 4; q++) {
                if (c[q] > CLO) {
                    atomicAdd(&shc[binhi10(c[q])], 1u);
                    int p = atomicAdd(&wctr[warp], 1);
                    if (p < SEGCAP)
                        mystage[p] = ((unsigned long long)__float_as_uint(c[q]) << 32)
                                   | (unsigned long long)(~(idx0 + 40960u + q));
                }
            }
        }
    }
    __syncthreads();

    if (t == 0) {
        int run = 0;
        #pragma unroll
        for (int w = 0; w < 32; w++) {
            woff[w] = run;
            int n = wctr[w];
            run += (n > SEGCAP ? SEGCAP : n);
        }
        bbase = atomicAdd(&g_cnt[b * CSTRIDE], run);
    }
    if (t < 32 && wctr[t] > SEGCAP) g_cnt[b * CSTRIDE + 1] = 1;
    __syncthreads();

    int n = wctr[warp]; if (n > SEGCAP) n = SEGCAP;
    unsigned long long* dst = g_cand + (size_t)b * CAPB + bbase + woff[warp];
    for (int off = lane; off < n; off += 32) dst[off] = mystage[off];
    if (shc[t]) atomicAdd(&g_coarse[b * NB2 + t], shc[t]);
}

// bitonic register step: element index i, phase k2, distance j (<32)
__device__ __forceinline__ unsigned long long bstep(
    unsigned long long v, int i, int k2, int j) {
    unsigned long long o = __shfl_xor_sync(0xffffffffu, v, j);
    bool keepmax = (((i & k2) == 0) == ((i & j) == 0));
    unsigned long long mx = v > o ? v : o;
    unsigned long long mn = v > o ? o : v;
    return keepmax ? mx : mn;
}

// one-warp descending sort of cnt (<=32) u64 keys in-place
__device__ __forceinline__ void warp_sort32(unsigned long long* base, int cnt, int lane) {
    unsigned long long v = (lane < cnt) ? base[lane] : 0ull;
    #pragma unroll
    for (int k2 = 2; k2 <= 32; k2 <<= 1)
        #pragma unroll
        for (int j = k2 >> 1; j >= 1; j >>= 1)
            v = bstep(v, lane, k2, j);
    if (lane < cnt) base[lane] = v;
}

// one-warp descending sort of cnt (<=128) u64 keys in-place
__device__ __forceinline__ void warp_sort128(unsigned long long* base, int cnt, int lane) {
    unsigned long long v[4];
    #pragma unroll
    for (int r = 0; r < 4; r++) {
        int e = r * 32 + lane;
        v[r] = (e < cnt) ? base[e] : 0ull;
    }
    #pragma unroll
    for (int k2 = 2; k2 <= 128; k2 <<= 1) {
        #pragma unroll
        for (int j = 64; j >= 32; j >>= 1) {
            if (j < k2) {
                int jr = j >> 5;
                #pragma unroll
                for (int r = 0; r < 4; r++) {
                    if ((r & jr) == 0) {
                        int pr = r | jr;
                        int e = r * 32 + lane;
                        bool desc = ((e & k2) == 0);
                        unsigned long long lo = v[r], hi = v[pr];
                        unsigned long long mx = lo > hi ? lo : hi;
                        unsigned long long mn = lo > hi ? hi : lo;
                        v[r]  = desc ? mx : mn;
                        v[pr] = desc ? mn : mx;
                    }
                }
            }
        }
        #pragma unroll
        for (int j = 16; j >= 1; j >>= 1) {
            if (j <= (k2 >> 1)) {
                #pragma unroll
                for (int r = 0; r < 4; r++)
                    v[r] = bstep(v[r], r * 32 + lane, k2, j);
            }
        }
    }
    #pragma unroll
    for (int r = 0; r < 4; r++) {
        int e = r * 32 + lane;
        if (e < cnt) base[e] = v[r];
    }
}

// ---------------- kernel 2: bucket-select + warp sorts + NMS + output -------
// key u64 = (float_bits << 32) | ~flat_idx, descending ->
// score desc, flat idx ascending on ties (matches lax.top_k stability).
// Cross-class IoU is exactly 0 (class offset gap), so global greedy ==
// independent per-class greedy in global-rank order. IoU ops identical to
// reference: offset coords, strict > 0.7, __f*_rn arithmetic.
__global__ void __launch_bounds__(1024) k_sortnms(const float4* __restrict__ boxes,
                                                  const float4* __restrict__ s4,
                                                  float* __restrict__ out) {
    extern __shared__ unsigned long long sm[];       // CAP u64 = 64 KB dynamic
    __shared__ int scnt, sT, sSuffT, sMaxSeg;
    __shared__ unsigned sstart[NB2];                 // 4 KB
    __shared__ unsigned binpos[NB2];                 // 4 KB
    __shared__ float sy1[TOPK], sx1[TOPK], sy2[TOPK], sx2[TOPK], sa[TOPK];
    __shared__ unsigned short wcount[NCLS * 32];
    __shared__ unsigned short wbase [NCLS * 32];
    __shared__ unsigned short ctot[NCLS];
    __shared__ unsigned short cstart[NCLS];
    __shared__ unsigned short list[TOPK];
    __shared__ unsigned char  skept[TOPK];
    __shared__ unsigned kw[32];
    __shared__ int kpref[33];

    int b = blockIdx.x;
    int t = threadIdx.x;
    int warp = t >> 5, lane = t & 31;
    const int perb4 = NCF / 4;
    int rawcnt = g_cnt[b * CSTRIDE];
    int ovf    = g_cnt[b * CSTRIDE + 1];

    if (t == 0) { scnt = 0; sT = 0; sSuffT = 0; sMaxSeg = 0; }
    sstart[t] = g_coarse[b * NB2 + t];               // counts for layout
    __syncthreads();

    unsigned long long* cand = g_cand + (size_t)b * CAPB;
    bool hot0 = (rawcnt >= TOPK && rawcnt <= CAPB && !ovf);
    bool hot = false;

    if (hot0) {
        // ---- warp-0: in-place suffix layout over 1024 bins ----
        if (warp == 0) {
            unsigned gsum = 0;
            #pragma unroll
            for (int k = 0; k < 32; k++) gsum += sstart[lane * 32 + k];
            unsigned acc = gsum;
            #pragma unroll
            for (int off = 1; off < 32; off <<= 1) {
                unsigned y = __shfl_down_sync(0xffffffffu, acc, off);
                if (lane + off < 32) acc += y;
            }
            unsigned above = acc - gsum;             // elements in higher groups
            unsigned run = above;
            int localT = -1;
            unsigned localSuff = 0;
            #pragma unroll
            for (int k = 31; k >= 0; k--) {
                int bin = lane * 32 + k;
                unsigned cv = sstart[bin];
                sstart[bin] = run;                   // start offset (suffix layout)
                run += cv;
                if (localT < 0 && run >= TOPK) { localT = bin; localSuff = run; }
            }
            unsigned mb = __ballot_sync(0xffffffffu, localT >= 0);
            int selLane = 31 - __clz((int)mb);
            int T = __shfl_sync(0xffffffffu, localT, selLane);
            unsigned suffT = __shfl_sync(0xffffffffu, (unsigned)localSuff, selLane);
            __syncwarp();
            unsigned mx = 0;
            for (int bin = T + lane; bin < NB2; bin += 32) {
                unsigned up = (bin == 0) ? (unsigned)rawcnt : sstart[bin - 1];
                unsigned cv = up - sstart[bin];
                if (cv > mx) mx = cv;
            }
            #pragma unroll
            for (int off = 16; off >= 1; off >>= 1)
                mx = max(mx, __shfl_xor_sync(0xffffffffu, mx, off));
            if (lane == 0) { sT = T; sSuffT = (int)suffT; sMaxSeg = (int)mx; }
        }
        __syncthreads();
        const int T = sT;
        const int suffT = sSuffT;
        hot = (suffT <= CAP);
        if (hot) {
            binpos[t] = sstart[t];
            __syncthreads();
            // ---- scatter pass: bin >= T -> exact segment position ----
            #pragma unroll 8
            for (int i = t; i < rawcnt; i += 1024) {
                unsigned long long k = cand[i];
                int bi = (int)binhi10(__uint_as_float((unsigned)(k >> 32)));
                if (bi >= T) {
                    int p = atomicAdd(&binpos[bi], 1u);
                    sm[p] = k;
                }
            }
            __syncthreads();
            if (sMaxSeg <= 128) {
                // ---- independent per-warp sorts (mostly 32-wide) ----
                for (int bin = T + warp; bin < NB2; bin += 32) {
                    int cnt = (int)(binpos[bin] - sstart[bin]);
                    if (cnt > 1) {
                        if (cnt <= 32) warp_sort32(sm + sstart[bin], cnt, lane);
                        else           warp_sort128(sm + sstart[bin], cnt, lane);
                    }
                }
                __syncthreads();
            } else {
                int n2 = 2048;
                while (n2 < suffT) n2 <<= 1;
                for (int i = t; i < n2; i += 1024) if (i >= suffT) sm[i] = 0ull;
                __syncthreads();
                for (int k2 = 2; k2 <= n2; k2 <<= 1) {
                    for (int j = k2 >> 1; j > 0; j >>= 1) {
                        for (int i = t; i < n2; i += 1024) {
                            int ixj = i ^ j;
                            if (ixj > i) {
                                unsigned long long x = sm[i], y = sm[ixj];
                                bool desc = ((i & k2) == 0);
                                if (desc ? (x < y) : (x > y)) { sm[i] = y; sm[ixj] = x; }
                            }
                        }
                        __syncthreads();
                    }
                }
            }
        }
    }

    if (!hot) {
        // ---- cold: full-range fine histogram + collect (always correct) ----
        unsigned* sh = (unsigned*)sm;                // 64 KB = HWORDS u32
        for (int i = t; i < HWORDS; i += 1024) sh[i] = 0;
        __syncthreads();
        const float4* src = s4 + (size_t)b * perb4;
        for (int i = t; i < perb4; i += 1024) {
            float4 v = src[i];
            float comp[4] = {v.x, v.y, v.z, v.w};
            #pragma unroll
            for (int q = 0; q < 4; q++) {
                unsigned k = binlo2(comp[q]);
                atomicAdd(&sh[k >> 1], 1u << ((k & 1) * 16));
            }
        }
        __syncthreads();
        if (t < 256) {
            unsigned sum = 0;
            for (int k = 0; k < 64; k++) {
                unsigned m = sh[t * 64 + k];
                sum += (m & 0xFFFFu) + (m >> 16);
            }
            sstart[t] = sum;
        }
        __syncthreads();
        if (t == 0) {
            unsigned h0 = sh[0] & 0xFFFFu;
            int sel = -1; unsigned cum = 0, cums = 0;
            for (int c = 255; c >= 0; c--) {
                unsigned cc = sstart[c] - (c == 0 ? h0 : 0u);
                if (cum + cc >= TOPK) { sel = c; cums = cum; break; }
                cum += cc;
            }
            int T = 1;
            if (sel >= 0) {
                unsigned cum2 = cums;
                int lo = (sel == 0) ? 1 : 0;
                for (int fb = 127; fb >= lo; fb--) {
                    int bin = (sel << 7) + fb;
                    unsigned m = sh[bin >> 1];
                    unsigned cc = (bin & 1) ? (m >> 16) : (m & 0xFFFFu);
                    cum2 += cc;
                    if (cum2 >= TOPK) { T = bin; break; }
                }
            }
            sT = T;
        }
        __syncthreads();
        unsigned T = (unsigned)sT;
        for (int i = t; i < perb4; i += 1024) {
            float4 v = src[i];
            float comp[4] = {v.x, v.y, v.z, v.w};
            #pragma unroll
            for (int q = 0; q < 4; q++) {
                float sv = comp[q];
                if (binlo2(sv) >= T) {
                    int p = atomicAdd(&scnt, 1);
                    if (p < CAPB) {
                        unsigned idx = (unsigned)(i * 4 + q);
                        cand[p] = ((unsigned long long)__float_as_uint(sv) << 32)
                                | (unsigned long long)(~idx);
                    }
                }
            }
        }
        __syncthreads();
        int cc = scnt; if (cc > CAP) cc = CAP;
        for (int i = t; i < cc; i += 1024) sm[i] = cand[i];
        __syncthreads();
        int n2 = 2048;
        while (n2 < cc) n2 <<= 1;
        for (int i = t; i < n2; i += 1024) if (i >= cc) sm[i] = 0ull;
        __syncthreads();
        for (int k2 = 2; k2 <= n2; k2 <<= 1) {
            for (int j = k2 >> 1; j > 0; j >>= 1) {
                for (int i = t; i < n2; i += 1024) {
                    int ixj = i ^ j;
                    if (ixj > i) {
                        unsigned long long x = sm[i], y = sm[ixj];
                        bool desc = ((i & k2) == 0);
                        if (desc ? (x < y) : (x > y)) { sm[i] = y; sm[ixj] = x; }
                    }
                }
                __syncthreads();
            }
        }
    }

    // ---- gather top-1024 boxes (registers) + build offset coords ----
    float4 mybox = make_float4(0.f, 0.f, 0.f, 0.f);
    int c = 0; float sc = 0.f;
    {
        unsigned long long kk = sm[t];
        unsigned keyhi = (unsigned)(kk >> 32);
        if (keyhi != 0) {
            unsigned idx = ~(unsigned)(kk & 0xFFFFFFFFull);
            int n = (int)(idx / NCLS);
            c = (int)(idx % NCLS);
            sc = __uint_as_float(keyhi);
            mybox = boxes[b * NN + n];
        }
        float off = (float)c * 4096.0f;              // exact in fp32
        float y1 = __fadd_rn(mybox.x, off);
        float x1 = __fadd_rn(mybox.y, off);
        float y2 = __fadd_rn(mybox.z, off);
        float x2 = __fadd_rn(mybox.w, off);
        sy1[t] = y1; sx1[t] = x1; sy2[t] = y2; sx2[t] = x2;
        sa[t] = __fmul_rn(__fadd_rn(__fsub_rn(x2, x1), 1.0f),
                          __fadd_rn(__fsub_rn(y2, y1), 1.0f));
    }
    bool valid = (sc > THRS);
    unsigned bal = __ballot_sync(0xffffffff, valid);
    if (lane == 0) kw[warp] = bal;
    for (int i = t; i < NCLS * 32; i += 1024) wcount[i] = 0;
    skept[t] = 1;
    __syncthreads();

    // ---- stable per-class list build (parallel scans) ----
    int cc2 = valid ? c : 0x7FFF;
    unsigned mm = __match_any_sync(0xffffffffu, cc2);
    int rank = __popc(mm & ((1u << lane) - 1u));
    int ldr = __ffs(mm) - 1;
    if (valid && lane == ldr) wcount[cc2 * 32 + warp] = (unsigned short)__popc(mm);
    __syncthreads();
    for (int c2 = warp; c2 < NCLS; c2 += 32) {
        unsigned v = wcount[c2 * 32 + lane];
        unsigned x = v;
        #pragma unroll
        for (int o = 1; o < 32; o <<= 1) {
            unsigned y = __shfl_up_sync(0xffffffffu, x, o);
            if (lane >= o) x += y;
        }
        wbase[c2 * 32 + lane] = (unsigned short)(x - v);
        if (lane == 31) ctot[c2] = (unsigned short)x;
    }
    __syncthreads();
    if (warp == 0) {
        unsigned a0 = ctot[lane];
        unsigned a1 = ctot[lane + 32];
        unsigned a2 = (lane + 64 < NCLS) ? ctot[lane + 64] : 0u;
        unsigned s0 = a0, s1 = a1, s2 = a2;
        #pragma unroll
        for (int o = 1; o < 32; o <<= 1) {
            unsigned y0 = __shfl_up_sync(0xffffffffu, s0, o);
            unsigned y1 = __shfl_up_sync(0xffffffffu, s1, o);
            unsigned y2 = __shfl_up_sync(0xffffffffu, s2, o);
            if (lane >= o) { s0 += y0; s1 += y1; s2 += y2; }
        }
        unsigned A0 = __shfl_sync(0xffffffffu, s0, 31);
        unsigned A1 = __shfl_sync(0xffffffffu, s1, 31);
        cstart[lane]      = (unsigned short)(s0 - a0);
        cstart[lane + 32] = (unsigned short)(A0 + s1 - a1);
        if (lane + 64 < NCLS) cstart[lane + 64] = (unsigned short)(A0 + A1 + s2 - a2);
    }
    __syncthreads();
    if (valid) list[cstart[cc2] + wbase[cc2 * 32 + warp] + rank] = (unsigned short)t;
    __syncthreads();

    // ---- per-class greedy (one warp per class; two-phase shfl) ----
    for (int c2 = warp; c2 < NCLS; c2 += 32) {
        int m = ctot[c2];
        if (m < 2) continue;
        int base = cstart[c2];
        if (m <= 32) {
            int tj = 0;
            float jy1 = 0, jx1 = 0, jy2 = 0, jx2 = 0, ja = 0;
            bool inr = (lane < m);
            if (inr) {
                tj = list[base + lane];
                jy1 = sy1[tj]; jx1 = sx1[tj]; jy2 = sy2[tj]; jx2 = sx2[tj]; ja = sa[tj];
            }
            unsigned sup = 0;
            for (int i = 0; i < m - 1; i++) {
                float iy1 = __shfl_sync(0xffffffffu, jy1, i);
                float ix1 = __shfl_sync(0xffffffffu, jx1, i);
                float iy2 = __shfl_sync(0xffffffffu, jy2, i);
                float ix2 = __shfl_sync(0xffffffffu, jx2, i);
                float ia  = __shfl_sync(0xffffffffu, ja,  i);
                if (lane > i) {
                    float yy1 = fmaxf(iy1, jy1);
                    float xx1 = fmaxf(ix1, jx1);
                    float yy2 = fminf(iy2, jy2);
                    float xx2 = fminf(ix2, jx2);
                    float ww = fmaxf(0.0f, __fadd_rn(__fsub_rn(xx2, xx1), 1.0f));
                    float hh = fmaxf(0.0f, __fadd_rn(__fsub_rn(yy2, yy1), 1.0f));
                    float inter = __fmul_rn(ww, hh);
                    float iou = __fdiv_rn(inter, __fsub_rn(__fadd_rn(ia, ja), inter));
                    if (iou > IOUT) sup |= (1u << i);
                }
            }
            unsigned anysup = __ballot_sync(0xffffffffu, inr && sup != 0u);
            bool kept = inr;
            if (anysup) {
                unsigned keptmask = 0;
                for (int i = 0; i < m; i++) {
                    unsigned si = __shfl_sync(0xffffffffu, sup, i);
                    unsigned bit = ((si & keptmask) == 0u) ? 1u : 0u;
                    keptmask |= bit << i;
                }
                kept = inr && ((keptmask >> lane) & 1u);
            }
            if (inr && !kept) atomicAnd(&kw[tj >> 5], ~(1u << (tj & 31)));
        } else {
            for (int i = 0; i < m - 1; i++) {
                __syncwarp();
                if (!skept[base + i]) continue;
                int ti = list[base + i];
                float iy1 = sy1[ti], ix1 = sx1[ti], iy2 = sy2[ti], ix2 = sx2[ti], ia = sa[ti];
                for (int k = i + 1 + lane; k < m; k += 32) {
                    if (skept[base + k]) {
                        int tk = list[base + k];
                        float yy1 = fmaxf(iy1, sy1[tk]);
                        float xx1 = fmaxf(ix1, sx1[tk]);
                        float yy2 = fminf(iy2, sy2[tk]);
                        float xx2 = fminf(ix2, sx2[tk]);
                        float ww = fmaxf(0.0f, __fadd_rn(__fsub_rn(xx2, xx1), 1.0f));
                        float hh = fmaxf(0.0f, __fadd_rn(__fsub_rn(yy2, yy1), 1.0f));
                        float inter = __fmul_rn(ww, hh);
                        float iou = __fdiv_rn(inter, __fsub_rn(__fadd_rn(ia, sa[tk]), inter));
                        if (iou > IOUT) skept[base + k] = 0;
                    }
                }
            }
            __syncwarp();
            for (int k = lane; k < m; k += 32)
                if (!skept[base + k]) {
                    int tk = list[base + k];
                    atomicAnd(&kw[tk >> 5], ~(1u << (tk & 31)));
                }
        }
    }
    __syncthreads();

    // ---- ranking + output ----
    if (t < 32) {
        unsigned my = kw[t];
        int p = __popc(my);
        int x = p;
        #pragma unroll
        for (int o = 1; o < 32; o <<= 1) {
            int y = __shfl_up_sync(0xffffffff, x, o);
            if (t >= o) x += y;
        }
        kpref[t] = x - p;
        if (t == 31) kpref[32] = x;
    }
    __syncthreads();

    int w = t >> 5, l = t & 31;
    unsigned kwv = kw[w];
    bool kept = (kwv >> l) & 1u;
    unsigned lowm = (l == 0) ? 0u : ((1u << l) - 1u);
    int TKall = kpref[32];

    int slot = -1;
    float oscore = 0.0f;
    if (kept) {
        int kr = kpref[w] + __popc(kwv & lowm);
        if (kr < NDET) { slot = kr; oscore = sc; }
    } else {
        int sr = (w << 5) - kpref[w] + __popc((~kwv) & lowm);
        int s2 = TKall + sr;
        if (s2 < NDET) { slot = s2; oscore = 0.0f; }
    }

    // output layout (float32): boxes[32,300,4] | scores[32,300] | labels[32,300] | n_valid[32,1]
    if (slot >= 0) {
        float* ob = out + ((size_t)b * NDET + slot) * 4;
        ob[0] = mybox.x; ob[1] = mybox.y; ob[2] = mybox.z; ob[3] = mybox.w;
        out[NB * NDET * 4 + b * NDET + slot] = oscore;
        out[NB * NDET * 5 + b * NDET + slot] = (float)c;
    }
    // reset per-replay state
    g_coarse[b * NB2 + t] = 0;
    if (t == 0) {
        out[NB * NDET * 6 + b] = (float)(TKall < NDET ? TKall : NDET);
        g_cnt[b * CSTRIDE] = 0;
        g_cnt[b * CSTRIDE + 1] = 0;
    }
}

// ---------------- launch ----------------------------------------------------
extern "C" void kernel_launch(void* const* d_in, const int* in_sizes, int n_in,
                              void* d_out, int out_size) {
    const float* boxes  = (const float*)d_in[0];
    const float* scores = (const float*)d_in[1];
    if (n_in >= 2 && in_sizes[0] > in_sizes[1]) {
        boxes  = (const float*)d_in[1];
        scores = (const float*)d_in[0];
    }
    float* out = (float*)d_out;

    cudaFuncSetAttribute(k_sortnms, cudaFuncAttributeMaxDynamicSharedMemorySize, CAP * 8);

    k_scan   <<<dim3(HSLICES, NB), 1024>>>((const float4*)scores);
    k_sortnms<<<NB, 1024, CAP * 8>>>((const float4*)boxes, (const float4*)scores, out);
}